// round 1
// baseline (speedup 1.0000x reference)
#include <cuda_runtime.h>
#include <cstdint>

#define ALPHA 0.2f
#define BN_EPS 1e-5f
#define MAXN 50176  // padded capacity for N=50000

// ---------------- scratch (device globals; no allocation allowed) ----------------
__device__ float g_z[(size_t)MAXN * 128];     // z = (1+eps)*self + weighted_neigh
__device__ float g_bufA[(size_t)MAXN * 128];
__device__ float g_bufB[(size_t)MAXN * 128];
__device__ float g_wa[128];                   // W_t @ a_neigh
__device__ float g_ws[128];                   // W_t @ a_self
__device__ float g_sum[3 * 128];
__device__ float g_sqs[3 * 128];
__device__ float g_scale[3 * 128];
__device__ float g_shift[3 * 128];

__device__ __forceinline__ float lrelu(float x) { return x > 0.f ? x : ALPHA * x; }

// ---------------- prep: wa, ws, zero stats ----------------
__global__ void prep_kernel(const float* __restrict__ W, const float* __restrict__ a_att) {
    int d = threadIdx.x;  // 0..127
    float wa = 0.f, ws = 0.f;
    #pragma unroll 8
    for (int t = 0; t < 128; ++t) {
        float w = W[d * 128 + t];
        ws += w * a_att[t];
        wa += w * a_att[128 + t];
    }
    g_wa[d] = wa;
    g_ws[d] = ws;
    #pragma unroll
    for (int l = 0; l < 3; ++l) { g_sum[l * 128 + d] = 0.f; g_sqs[l * 128 + d] = 0.f; }
}

// ---------------- fused attention: scores -> softmax -> weighted sum -> z ----------------
// one block (128 threads / 4 warps) per node n. K <= 28 assumed (K=25).
__global__ __launch_bounds__(128) void attn_kernel(
    const float* __restrict__ self, const float* __restrict__ neigh,
    const float* __restrict__ epsp, int N, int K)
{
    __shared__ float s_raw[32];
    __shared__ float s_attn[32];
    __shared__ float s_sred[4];
    __shared__ float4 s_part[4][32];

    int n = blockIdx.x;
    int tid = threadIdx.x, warp = tid >> 5, lane = tid & 31;

    const float4* nb = (const float4*)neigh + (size_t)n * K * 32;
    const float4* sv = (const float4*)self + (size_t)n * 32;

    float4 wa4 = ((const float4*)g_wa)[lane];

    // self score: s_self = self[n] . ws  (block reduce)
    float sp = self[(size_t)n * 128 + tid] * g_ws[tid];
    #pragma unroll
    for (int off = 16; off; off >>= 1) sp += __shfl_xor_sync(0xffffffffu, sp, off);
    if (lane == 0) s_sred[warp] = sp;

    // load this warp's neighbor rows into registers (k = warp + 4*j)
    float4 v[7];
    #pragma unroll
    for (int j = 0; j < 7; ++j) {
        int k = warp + 4 * j;
        v[j] = (k < K) ? nb[k * 32 + lane] : make_float4(0.f, 0.f, 0.f, 0.f);
    }

    // raw neighbor scores: neigh[n,k] . wa
    #pragma unroll
    for (int j = 0; j < 7; ++j) {
        int k = warp + 4 * j;
        if (k < K) {
            float s = v[j].x * wa4.x + v[j].y * wa4.y + v[j].z * wa4.z + v[j].w * wa4.w;
            #pragma unroll
            for (int off = 16; off; off >>= 1) s += __shfl_xor_sync(0xffffffffu, s, off);
            if (lane == 0) s_raw[k] = s;
        }
    }
    __syncthreads();

    // warp 0: leaky_relu + softmax over K
    if (warp == 0) {
        float ssum = s_sred[0] + s_sred[1] + s_sred[2] + s_sred[3];
        float val = -1e30f;
        if (lane < K) val = lrelu(ssum + s_raw[lane]);
        float m = val;
        #pragma unroll
        for (int off = 16; off; off >>= 1) m = fmaxf(m, __shfl_xor_sync(0xffffffffu, m, off));
        float e = (lane < K) ? expf(val - m) : 0.f;
        float s = e;
        #pragma unroll
        for (int off = 16; off; off >>= 1) s += __shfl_xor_sync(0xffffffffu, s, off);
        s_attn[lane] = e / s;
    }
    __syncthreads();

    // weighted sum over this warp's k's (rows still in registers)
    float4 acc = make_float4(0.f, 0.f, 0.f, 0.f);
    #pragma unroll
    for (int j = 0; j < 7; ++j) {
        int k = warp + 4 * j;
        if (k < K) {
            float a = s_attn[k];
            acc.x += a * v[j].x; acc.y += a * v[j].y;
            acc.z += a * v[j].z; acc.w += a * v[j].w;
        }
    }
    s_part[warp][lane] = acc;
    __syncthreads();

    // warp 0: cross-warp reduce + (1+eps)*self, write z
    if (warp == 0) {
        float4 r0 = s_part[0][lane], r1 = s_part[1][lane];
        float4 r2 = s_part[2][lane], r3 = s_part[3][lane];
        float ce = 1.f + epsp[0];
        float4 sf = sv[lane];
        float4 r;
        r.x = r0.x + r1.x + r2.x + r3.x + ce * sf.x;
        r.y = r0.y + r1.y + r2.y + r3.y + ce * sf.y;
        r.z = r0.z + r1.z + r2.z + r3.z + ce * sf.z;
        r.w = r0.w + r1.w + r2.w + r3.w + ce * sf.w;
        ((float4*)g_z)[(size_t)n * 32 + lane] = r;
    }
}

// ---------------- GEMM [N,128] @ [128,128] with fused input-BN and column stats ----------------
// BM=64 rows per block, full 128 cols, BK=32, 256 threads, TM=8 x TN=4 per thread.
template <bool IN_BN, bool BIAS, bool STATS>
__global__ __launch_bounds__(256) void gemm_fused(
    const float* __restrict__ A, const float* __restrict__ W, const float* __restrict__ bias,
    const float* __restrict__ scaleIn, const float* __restrict__ shiftIn,
    float* __restrict__ Y, float* __restrict__ sumOut, float* __restrict__ sqsOut, int N)
{
    __shared__ float As[64 * 36];    // [m][kk], padded stride 36
    __shared__ float Ws[32 * 132];   // [kk][c], padded stride 132
    __shared__ float red[8 * 128];

    const int tid = threadIdx.x;
    const int cg = tid & 31;   // column group: cols cg*4..cg*4+3
    const int rg = tid >> 5;   // row group (warp): rows rg*8..rg*8+7
    const int rowBase = blockIdx.x * 64;

    const float4* Ag4 = (const float4*)A;
    const float4* Wg4 = (const float4*)W;

    float acc[8][4];
    #pragma unroll
    for (int i = 0; i < 8; ++i)
        #pragma unroll
        for (int j = 0; j < 4; ++j) acc[i][j] = 0.f;

    for (int ch = 0; ch < 4; ++ch) {
        // load W chunk: rows ch*32..ch*32+31, all 128 cols
        #pragma unroll
        for (int i = 0; i < 4; ++i) {
            int j = tid + i * 256;       // 0..1023 float4 slots
            int kk = j >> 5, cq = j & 31;
            float4 w = Wg4[(ch * 32 + kk) * 32 + cq];
            *(float4*)&Ws[kk * 132 + cq * 4] = w;
        }
        // load A chunk: 64 rows x 32 k
        #pragma unroll
        for (int i = 0; i < 2; ++i) {
            int j = tid + i * 256;       // 0..511 float4 slots
            int m = j >> 3, kq = j & 7;
            int grow = rowBase + m;
            float4 a = make_float4(0.f, 0.f, 0.f, 0.f);
            if (grow < N) a = Ag4[(size_t)grow * 32 + ch * 8 + kq];
            if (IN_BN) {
                float4 sc = ((const float4*)scaleIn)[ch * 8 + kq];
                float4 sh = ((const float4*)shiftIn)[ch * 8 + kq];
                a.x = lrelu(sc.x * a.x + sh.x);
                a.y = lrelu(sc.y * a.y + sh.y);
                a.z = lrelu(sc.z * a.z + sh.z);
                a.w = lrelu(sc.w * a.w + sh.w);
            }
            *(float4*)&As[m * 36 + kq * 4] = a;
        }
        __syncthreads();

        const float* Arow = &As[rg * 8 * 36];
        #pragma unroll
        for (int kk = 0; kk < 32; ++kk) {
            float4 b4 = *(const float4*)&Ws[kk * 132 + cg * 4];
            #pragma unroll
            for (int i = 0; i < 8; ++i) {
                float a = Arow[i * 36 + kk];
                acc[i][0] += a * b4.x;
                acc[i][1] += a * b4.y;
                acc[i][2] += a * b4.z;
                acc[i][3] += a * b4.w;
            }
        }
        __syncthreads();
    }

    // epilogue
    float4 bi = make_float4(0.f, 0.f, 0.f, 0.f);
    if (BIAS) bi = ((const float4*)bias)[cg];
    float colSum[4] = {0.f, 0.f, 0.f, 0.f};
    float colSq[4]  = {0.f, 0.f, 0.f, 0.f};

    #pragma unroll
    for (int i = 0; i < 8; ++i) {
        int grow = rowBase + rg * 8 + i;
        if (grow < N) {
            float4 y;
            y.x = acc[i][0] + bi.x;
            y.y = acc[i][1] + bi.y;
            y.z = acc[i][2] + bi.z;
            y.w = acc[i][3] + bi.w;
            ((float4*)Y)[(size_t)grow * 32 + cg] = y;
            if (STATS) {
                colSum[0] += y.x; colSum[1] += y.y; colSum[2] += y.z; colSum[3] += y.w;
                colSq[0] += y.x * y.x; colSq[1] += y.y * y.y;
                colSq[2] += y.z * y.z; colSq[3] += y.w * y.w;
            }
        }
    }

    if (STATS) {
        *(float4*)&red[rg * 128 + cg * 4] = make_float4(colSum[0], colSum[1], colSum[2], colSum[3]);
        __syncthreads();
        if (tid < 32) {
            #pragma unroll
            for (int j = 0; j < 4; ++j) {
                float t = 0.f;
                #pragma unroll
                for (int r = 0; r < 8; ++r) t += red[r * 128 + tid * 4 + j];
                atomicAdd(&sumOut[tid * 4 + j], t);
            }
        }
        __syncthreads();
        *(float4*)&red[rg * 128 + cg * 4] = make_float4(colSq[0], colSq[1], colSq[2], colSq[3]);
        __syncthreads();
        if (tid < 32) {
            #pragma unroll
            for (int j = 0; j < 4; ++j) {
                float t = 0.f;
                #pragma unroll
                for (int r = 0; r < 8; ++r) t += red[r * 128 + tid * 4 + j];
                atomicAdd(&sqsOut[tid * 4 + j], t);
            }
        }
    }
}

// ---------------- BN finalize: per-column scale/shift ----------------
__global__ void bn_fin_kernel(const float* __restrict__ sum, const float* __restrict__ sqs,
                              const float* __restrict__ g, const float* __restrict__ be,
                              float* __restrict__ scale, float* __restrict__ shift, float invN)
{
    int c = threadIdx.x;
    float m = sum[c] * invN;
    float var = sqs[c] * invN - m * m;
    float s = g[c] * rsqrtf(var + BN_EPS);
    scale[c] = s;
    shift[c] = be[c] - m * s;
}

// ---------------- final BN + leaky_relu apply ----------------
__global__ void apply_kernel(const float* __restrict__ Y,
                             const float* __restrict__ scale, const float* __restrict__ shift,
                             float* __restrict__ out, int N)
{
    size_t i = (size_t)blockIdx.x * blockDim.x + threadIdx.x;  // float4 index
    if (i < (size_t)N * 32) {
        int c = (int)(i & 31);
        float4 sc = ((const float4*)scale)[c];
        float4 sh = ((const float4*)shift)[c];
        float4 y = ((const float4*)Y)[i];
        float4 o;
        o.x = lrelu(sc.x * y.x + sh.x);
        o.y = lrelu(sc.y * y.y + sh.y);
        o.z = lrelu(sc.z * y.z + sh.z);
        o.w = lrelu(sc.w * y.w + sh.w);
        ((float4*)out)[i] = o;
    }
}

// ---------------- launch ----------------
extern "C" void kernel_launch(void* const* d_in, const int* in_sizes, int n_in,
                              void* d_out, int out_size) {
    const float* self  = (const float*)d_in[0];
    const float* neigh = (const float*)d_in[1];
    const float* W_t   = (const float*)d_in[2];
    const float* a_att = (const float*)d_in[3];
    const float* epsp  = (const float*)d_in[4];
    const float* W1 = (const float*)d_in[5];
    const float* b1 = (const float*)d_in[6];
    const float* g1 = (const float*)d_in[7];
    const float* be1 = (const float*)d_in[8];
    const float* W2 = (const float*)d_in[9];
    const float* b2 = (const float*)d_in[10];
    const float* g2 = (const float*)d_in[11];
    const float* be2 = (const float*)d_in[12];
    const float* W3 = (const float*)d_in[13];
    const float* b3 = (const float*)d_in[14];
    const float* g3 = (const float*)d_in[15];
    const float* be3 = (const float*)d_in[16];

    int N = in_sizes[0] / 128;
    int K = (int)((long long)in_sizes[1] / ((long long)N * 128));

    float *z, *bufA, *bufB, *sum, *sqs, *scale, *shift;
    cudaGetSymbolAddress((void**)&z,     g_z);
    cudaGetSymbolAddress((void**)&bufA,  g_bufA);
    cudaGetSymbolAddress((void**)&bufB,  g_bufB);
    cudaGetSymbolAddress((void**)&sum,   g_sum);
    cudaGetSymbolAddress((void**)&sqs,   g_sqs);
    cudaGetSymbolAddress((void**)&scale, g_scale);
    cudaGetSymbolAddress((void**)&shift, g_shift);

    float invN = 1.f / (float)N;
    int gemmGrid = (N + 63) / 64;

    prep_kernel<<<1, 128>>>(W_t, a_att);
    attn_kernel<<<N, 128>>>(self, neigh, epsp, N, K);

    // x0 = z @ W_t                          (bufA)
    gemm_fused<false, false, false><<<gemmGrid, 256>>>(
        z, W_t, nullptr, nullptr, nullptr, bufA, nullptr, nullptr, N);

    // y1 = x0 @ W1 + b1, stats layer 0      (bufB)
    gemm_fused<false, true, true><<<gemmGrid, 256>>>(
        bufA, W1, b1, nullptr, nullptr, bufB, sum, sqs, N);
    bn_fin_kernel<<<1, 128>>>(sum, sqs, g1, be1, scale, shift, invN);

    // y2 = act1(y1) @ W2 + b2, stats layer 1 (bufA)
    gemm_fused<true, true, true><<<gemmGrid, 256>>>(
        bufB, W2, b2, scale, shift, bufA, sum + 128, sqs + 128, N);
    bn_fin_kernel<<<1, 128>>>(sum + 128, sqs + 128, g2, be2, scale + 128, shift + 128, invN);

    // y3 = act2(y2) @ W3 + b3, stats layer 2 (bufB)
    gemm_fused<true, true, true><<<gemmGrid, 256>>>(
        bufA, W3, b3, scale + 128, shift + 128, bufB, sum + 256, sqs + 256, N);
    bn_fin_kernel<<<1, 128>>>(sum + 256, sqs + 256, g3, be3, scale + 256, shift + 256, invN);

    // out = act3(y3)
    int applyGrid = (int)(((size_t)N * 32 + 255) / 256);
    apply_kernel<<<applyGrid, 256>>>(bufB, scale + 256, shift + 256, (float*)d_out, N);
}